// round 9
// baseline (speedup 1.0000x reference)
#include <cuda_runtime.h>
#include <math.h>

#define NB 4096
#define ND 128
#define TILE 128
#define KC 32
#define LDW (TILE + 4)
#define MAXM 64
#define MARGINF 0.2f

__device__ double g_accum;
__device__ __align__(16) float g_sq[NB];
__device__ __align__(16) float g_sim[(size_t)NB * NB];  // 64 MB sim matrix

// ---------- packed f32x2 helpers ----------
__device__ __forceinline__ unsigned long long pk2(float lo, float hi) {
    unsigned long long r;
    asm("mov.b64 %0, {%1, %2};" : "=l"(r) : "f"(lo), "f"(hi));
    return r;
}
__device__ __forceinline__ void fma2(unsigned long long& d, unsigned long long a,
                                     unsigned long long b) {
    asm("fma.rn.f32x2 %0, %1, %2, %0;" : "+l"(d) : "l"(a), "l"(b));
}
__device__ __forceinline__ float2 upk2(unsigned long long v) {
    float2 r;
    asm("mov.b64 {%0, %1}, %2;" : "=f"(r.x), "=f"(r.y) : "l"(v));
    return r;
}

// Prep: squared norms + zero accumulator. One warp per row.
__global__ void prep_kernel(const float* __restrict__ X) {
    if (blockIdx.x == 0 && threadIdx.x == 0) g_accum = 0.0;
    int row = blockIdx.x * 8 + (threadIdx.x >> 5);
    int lane = threadIdx.x & 31;
    float4 v = ((const float4*)(X + (size_t)row * ND))[lane];
    float s = v.x * v.x + v.y * v.y + v.z * v.z + v.w * v.w;
    #pragma unroll
    for (int o = 16; o; o >>= 1) s += __shfl_xor_sync(0xffffffffu, s, o);
    if (lane == 0) g_sq[row] = s;
}

__device__ __forceinline__ float mksim(float si, float sj, float dot, bool mt) {
    float d2 = fmaxf(si + sj - 2.0f * dot, 0.0f);
    float s = (d2 == 0.0f) ? 0.0f : -sqrtf(d2);
    return mt ? s : s + MARGINF;
}

// ---------------- Kernel 2: tiled GEMM -> sim matrix ----------------
// Tile 128x128, K=128 in 4 chunks of 32, double-buffered smem.
// 256 threads; warp tile 32(m) x 64(n); thread microtile 8x8; packed FFMA2.
__global__ __launch_bounds__(256)
void gemm_sim_kernel(const float* __restrict__ X, const int* __restrict__ labels) {
    extern __shared__ __align__(16) char smraw[];
    float* Asp = (float*)smraw;            // 2 * KC * LDW
    float* Bsp = Asp + 2 * KC * LDW;       // 2 * KC * LDW
    float* sqA = Bsp + 2 * KC * LDW;       // 128
    float* sqB = sqA + TILE;               // 128
    int*   lbA = (int*)(sqB + TILE);       // 128
    int*   lbB = lbA + TILE;               // 128

    int tid = threadIdx.x;
    int bi = blockIdx.y, bj = blockIdx.x;
    int rowA = bi * TILE, rowB = bj * TILE;

    if (tid < 128) {
        sqA[tid] = g_sq[rowA + tid];
        lbA[tid] = labels[rowA + tid];
    } else {
        int t = tid - 128;
        sqB[t] = g_sq[rowB + t];
        lbB[t] = labels[rowB + t];
    }

    // chunk loader: X rows [rowbase, rowbase+128), cols [k0, k0+32) -> dst[k][m]
    auto load_chunk = [&](float* dst, int rowbase, int k0) {
        #pragma unroll
        for (int it = 0; it < 4; it++) {
            int idx = tid + 256 * it;
            int m = idx >> 3, q = idx & 7;
            float4 v = *(const float4*)(X + (size_t)(rowbase + m) * ND + k0 + 4 * q);
            dst[(4 * q + 0) * LDW + m] = v.x;
            dst[(4 * q + 1) * LDW + m] = v.y;
            dst[(4 * q + 2) * LDW + m] = v.z;
            dst[(4 * q + 3) * LDW + m] = v.w;
        }
    };

    load_chunk(Asp, rowA, 0);
    load_chunk(Bsp, rowB, 0);

    int wid = tid >> 5, lane = tid & 31;
    int mbase = (wid & 3) * 32 + (lane >> 3) * 8;  // 4 warps along m
    int nbase = (wid >> 2) * 64 + (lane & 7) * 8;  // 2 warps along n

    unsigned long long acc2[8][4];
    #pragma unroll
    for (int r = 0; r < 8; r++)
        #pragma unroll
        for (int p = 0; p < 4; p++) acc2[r][p] = 0ull;

    __syncthreads();
    #pragma unroll
    for (int ch = 0; ch < 4; ch++) {
        int cur = ch & 1, nxt = cur ^ 1;
        if (ch < 3) {
            load_chunk(Asp + nxt * KC * LDW, rowA, (ch + 1) * KC);
            load_chunk(Bsp + nxt * KC * LDW, rowB, (ch + 1) * KC);
        }
        const float* Ac = Asp + cur * KC * LDW;
        const float* Bc = Bsp + cur * KC * LDW;
        #pragma unroll
        for (int k = 0; k < KC; k++) {
            float4 a0 = *(const float4*)(Ac + k * LDW + mbase);
            float4 a1 = *(const float4*)(Ac + k * LDW + mbase + 4);
            ulonglong2 b0 = *(const ulonglong2*)(Bc + k * LDW + nbase);
            ulonglong2 b1 = *(const ulonglong2*)(Bc + k * LDW + nbase + 4);
            float av[8] = {a0.x, a0.y, a0.z, a0.w, a1.x, a1.y, a1.z, a1.w};
            #pragma unroll
            for (int r = 0; r < 8; r++) {
                unsigned long long ar = pk2(av[r], av[r]);
                fma2(acc2[r][0], ar, b0.x);
                fma2(acc2[r][1], ar, b0.y);
                fma2(acc2[r][2], ar, b1.x);
                fma2(acc2[r][3], ar, b1.y);
            }
        }
        __syncthreads();
    }

    // Epilogue: sim values + coalesced store.
    #pragma unroll
    for (int r = 0; r < 8; r++) {
        int ml = mbase + r;
        float sm_ = sqA[ml];
        int lm = lbA[ml];
        float vals[8];
        #pragma unroll
        for (int p = 0; p < 4; p++) {
            float2 d = upk2(acc2[r][p]);
            int n0 = nbase + 2 * p;
            vals[2 * p]     = mksim(sm_, sqB[n0],     d.x, lm == lbB[n0]);
            vals[2 * p + 1] = mksim(sm_, sqB[n0 + 1], d.y, lm == lbB[n0 + 1]);
        }
        float* dst = g_sim + (size_t)(rowA + ml) * NB + rowB + nbase;
        *(float4*)dst       = make_float4(vals[0], vals[1], vals[2], vals[3]);
        *(float4*)(dst + 4) = make_float4(vals[4], vals[5], vals[6], vals[7]);
    }
}

// ---------------- Kernel 3: per-row rank-aware selection ----------------
// One row per CTA, 256 threads, 16 sims/thread in registers.
__global__ __launch_bounds__(256, 8)
void phaseB_kernel(const int* __restrict__ labels) {
    __shared__ float vm[MAXM];
    __shared__ int jm[MAXM];
    __shared__ int cnt[MAXM];
    __shared__ float rv[8];
    __shared__ int ri[8];
    __shared__ int rm[8];
    __shared__ int mcount;
    __shared__ int widx;

    const float NEG_INF = __int_as_float(0xff800000);
    int tid = threadIdx.x, lane = tid & 31, wid = tid >> 5;
    int row = blockIdx.x;
    const float* simr = g_sim + (size_t)row * NB;
    int lr = labels[row];
    if (tid == 0) mcount = 0;
    __syncthreads();

    float ls[16];
    int gj[16];
    unsigned mrow = 0;
    #pragma unroll
    for (int t = 0; t < 4; t++) {
        int j4 = tid + 256 * t;
        float4 s4 = *(const float4*)(simr + 4 * (size_t)j4);
        int4 l4 = *(const int4*)(labels + 4 * j4);
        int b = 4 * t;
        ls[b + 0] = s4.x; ls[b + 1] = s4.y; ls[b + 2] = s4.z; ls[b + 3] = s4.w;
        gj[b + 0] = 4 * j4 + 0; gj[b + 1] = 4 * j4 + 1;
        gj[b + 2] = 4 * j4 + 2; gj[b + 3] = 4 * j4 + 3;
        if (l4.x == lr) mrow |= 1u << (b + 0);
        if (l4.y == lr) mrow |= 1u << (b + 1);
        if (l4.z == lr) mrow |= 1u << (b + 2);
        if (l4.w == lr) mrow |= 1u << (b + 3);
    }

    // Gather matched elements.
    #pragma unroll
    for (int q = 0; q < 16; q++) {
        if ((mrow >> q) & 1u) {
            int p = atomicAdd(&mcount, 1);
            if (p < MAXM) { jm[p] = gj[q]; vm[p] = ls[q]; cnt[p] = 0; }
        }
    }
    __syncthreads();
    int k = mcount;
    if (k > MAXM) k = MAXM;

    // Count-based ranks for matched elements (rank = cnt+1, stable ties).
    for (int m = 0; m < k; m++) {
        float vmv = vm[m];
        int jmi = jm[m];
        int c = 0;
        #pragma unroll
        for (int q = 0; q < 16; q++)
            c += (ls[q] > vmv || (ls[q] == vmv && gj[q] < jmi)) ? 1 : 0;
        c = __reduce_add_sync(0xffffffffu, c);
        if (lane == 0) atomicAdd(&cnt[m], c);
    }

    // Extract top-k (stable tie-break: smaller index wins); e is the rank.
    float kf = (float)k;
    float fp_acc = 0.0f;  // tid 0 only
    for (int e = 1; e <= k; e++) {
        float bv = NEG_INF;
        int bi = 1 << 30;
        int bm = 0;
        #pragma unroll
        for (int q = 0; q < 16; q++) {
            float v = ls[q];
            if (v > bv || (v == bv && gj[q] < bi)) {
                bv = v; bi = gj[q]; bm = (mrow >> q) & 1;
            }
        }
        #pragma unroll
        for (int o = 16; o; o >>= 1) {
            float ov = __shfl_xor_sync(0xffffffffu, bv, o);
            int oi = __shfl_xor_sync(0xffffffffu, bi, o);
            int om = __shfl_xor_sync(0xffffffffu, bm, o);
            if (ov > bv || (ov == bv && oi < bi)) { bv = ov; bi = oi; bm = om; }
        }
        if (lane == 0) { rv[wid] = bv; ri[wid] = bi; rm[wid] = bm; }
        __syncthreads();
        if (tid == 0) {
            float wv = rv[0]; int wi2 = ri[0]; int wm = rm[0];
            #pragma unroll
            for (int w = 1; w < 8; w++)
                if (rv[w] > wv || (rv[w] == wv && ri[w] < wi2)) {
                    wv = rv[w]; wi2 = ri[w]; wm = rm[w];
                }
            widx = wi2;
            if (!wm)  // false positive at rank e
                fp_acc += wv * (0.5f + (kf - (float)e + 1.0f) / kf * 0.5f);
        }
        __syncthreads();
        int wi2 = widx;
        #pragma unroll
        for (int q = 0; q < 16; q++)
            if (gj[q] == wi2) ls[q] = NEG_INF;
        __syncthreads();
    }

    if (tid == 0) {
        float fn_acc = 0.0f;
        float nf = (float)NB;
        for (int m = 0; m < k; m++) {
            int rank = cnt[m] + 1;
            if (rank > k)
                fn_acc += vm[m] * (0.5f + ((float)rank - kf) / (nf - kf) * 0.5f);
        }
        atomicAdd(&g_accum, (double)(fp_acc - fn_acc));
    }
}

__global__ void out_kernel(float* out) {
    out[0] = (float)g_accum;
}

extern "C" void kernel_launch(void* const* d_in, const int* in_sizes, int n_in,
                              void* d_out, int out_size) {
    const float* X = (const float*)d_in[0];
    const int* labels = (const int*)d_in[1];
    float* out = (float*)d_out;

    size_t shmem = (size_t)4 * KC * LDW * 4   // As + Bs double-buffered
                 + 2 * TILE * 4               // sqA, sqB
                 + 2 * TILE * 4;              // lbA, lbB
    cudaFuncSetAttribute(gemm_sim_kernel,
                         cudaFuncAttributeMaxDynamicSharedMemorySize, (int)shmem);

    prep_kernel<<<NB / 8, 256>>>(X);
    gemm_sim_kernel<<<dim3(NB / TILE, NB / TILE), 256, shmem>>>(X, labels);
    phaseB_kernel<<<NB, 256>>>(labels);
    out_kernel<<<1, 1>>>(out);
}

// round 10
// speedup vs baseline: 2.3174x; 2.3174x over previous
#include <cuda_runtime.h>
#include <math.h>

#define NB 4096
#define ND 128
#define TILE 128
#define KC 32
#define LDW (TILE + 4)
#define MAXM 64
#define MARGINF 0.2f

__device__ double g_accum;
__device__ __align__(16) float g_sq[NB];
__device__ __align__(16) float g_sim[(size_t)NB * NB];  // 64 MB sim matrix

// Prep: squared norms + zero accumulator. One warp per row.
__global__ void prep_kernel(const float* __restrict__ X) {
    if (blockIdx.x == 0 && threadIdx.x == 0) g_accum = 0.0;
    int row = blockIdx.x * 8 + (threadIdx.x >> 5);
    int lane = threadIdx.x & 31;
    float4 v = ((const float4*)(X + (size_t)row * ND))[lane];
    float s = v.x * v.x + v.y * v.y + v.z * v.z + v.w * v.w;
    #pragma unroll
    for (int o = 16; o; o >>= 1) s += __shfl_xor_sync(0xffffffffu, s, o);
    if (lane == 0) g_sq[row] = s;
}

__device__ __forceinline__ float mksim(float si, float sj, float dot, bool mt) {
    float d2 = fmaxf(si + sj - 2.0f * dot, 0.0f);
    float s = (d2 == 0.0f) ? 0.0f : -sqrtf(d2);
    return mt ? s : s + MARGINF;
}

// ---------------- Kernel 2: symmetric tiled SGEMM -> sim matrix ----------------
// Upper-triangular tiles only (bi <= bj); mirror-store the transposed block.
// 256 threads; 8x8 microtile; scalar FFMA; double-buffered KC=32 smem.
__global__ __launch_bounds__(256, 2)
void gemm_sim_kernel(const float* __restrict__ X, const int* __restrict__ labels) {
    int bi = blockIdx.y, bj = blockIdx.x;
    if (bi > bj) return;  // symmetry: upper triangle only

    extern __shared__ __align__(16) char smraw[];
    float* Asp = (float*)smraw;            // 2 * KC * LDW
    float* Bsp = Asp + 2 * KC * LDW;       // 2 * KC * LDW
    float* sqA = Bsp + 2 * KC * LDW;       // 128
    float* sqB = sqA + TILE;               // 128
    int*   lbA = (int*)(sqB + TILE);       // 128
    int*   lbB = lbA + TILE;               // 128

    int tid = threadIdx.x;
    int rowA = bi * TILE, rowB = bj * TILE;

    if (tid < 128) {
        sqA[tid] = g_sq[rowA + tid];
        lbA[tid] = labels[rowA + tid];
    } else {
        int t = tid - 128;
        sqB[t] = g_sq[rowB + t];
        lbB[t] = labels[rowB + t];
    }

    // chunk loader: X rows [rowbase, rowbase+128), cols [k0, k0+32) -> dst[k][m]
    auto load_chunk = [&](float* dst, int rowbase, int k0) {
        #pragma unroll
        for (int it = 0; it < 4; it++) {
            int idx = tid + 256 * it;
            int m = idx >> 3, q = idx & 7;
            float4 v = *(const float4*)(X + (size_t)(rowbase + m) * ND + k0 + 4 * q);
            dst[(4 * q + 0) * LDW + m] = v.x;
            dst[(4 * q + 1) * LDW + m] = v.y;
            dst[(4 * q + 2) * LDW + m] = v.z;
            dst[(4 * q + 3) * LDW + m] = v.w;
        }
    };

    load_chunk(Asp, rowA, 0);
    load_chunk(Bsp, rowB, 0);

    int wid = tid >> 5, lane = tid & 31;
    int mbase = (wid & 3) * 32 + (lane >> 3) * 8;  // 4 warps along m
    int nbase = (wid >> 2) * 64 + (lane & 7) * 8;  // 2 warps along n

    float acc[8][8];
    #pragma unroll
    for (int r = 0; r < 8; r++)
        #pragma unroll
        for (int p = 0; p < 8; p++) acc[r][p] = 0.0f;

    __syncthreads();
    #pragma unroll
    for (int ch = 0; ch < 4; ch++) {
        int cur = ch & 1, nxt = cur ^ 1;
        if (ch < 3) {
            load_chunk(Asp + nxt * KC * LDW, rowA, (ch + 1) * KC);
            load_chunk(Bsp + nxt * KC * LDW, rowB, (ch + 1) * KC);
        }
        const float* Ac = Asp + cur * KC * LDW;
        const float* Bc = Bsp + cur * KC * LDW;
        #pragma unroll
        for (int k = 0; k < KC; k++) {
            float4 a0 = *(const float4*)(Ac + k * LDW + mbase);
            float4 a1 = *(const float4*)(Ac + k * LDW + mbase + 4);
            float4 b0 = *(const float4*)(Bc + k * LDW + nbase);
            float4 b1 = *(const float4*)(Bc + k * LDW + nbase + 4);
            float av[8] = {a0.x, a0.y, a0.z, a0.w, a1.x, a1.y, a1.z, a1.w};
            float bv[8] = {b0.x, b0.y, b0.z, b0.w, b1.x, b1.y, b1.z, b1.w};
            #pragma unroll
            for (int r = 0; r < 8; r++)
                #pragma unroll
                for (int p = 0; p < 8; p++)
                    acc[r][p] = fmaf(av[r], bv[p], acc[r][p]);
        }
        __syncthreads();
    }

    // Epilogue: sim values; store normal block and (if off-diagonal) mirror.
    float vals[8][8];
    #pragma unroll
    for (int r = 0; r < 8; r++) {
        int ml = mbase + r;
        float sm_ = sqA[ml];
        int lm = lbA[ml];
        #pragma unroll
        for (int p = 0; p < 8; p++) {
            int nl = nbase + p;
            vals[r][p] = mksim(sm_, sqB[nl], acc[r][p], lm == lbB[nl]);
        }
        float* dst = g_sim + (size_t)(rowA + ml) * NB + rowB + nbase;
        *(float4*)dst       = make_float4(vals[r][0], vals[r][1], vals[r][2], vals[r][3]);
        *(float4*)(dst + 4) = make_float4(vals[r][4], vals[r][5], vals[r][6], vals[r][7]);
    }
    if (bi != bj) {
        #pragma unroll
        for (int p = 0; p < 8; p++) {
            float* dst = g_sim + (size_t)(rowB + nbase + p) * NB + rowA + mbase;
            *(float4*)dst       = make_float4(vals[0][p], vals[1][p], vals[2][p], vals[3][p]);
            *(float4*)(dst + 4) = make_float4(vals[4][p], vals[5][p], vals[6][p], vals[7][p]);
        }
    }
}

// ---------------- Kernel 3: per-row rank-aware selection ----------------
// One row per CTA, 256 threads, 16 sims/thread in registers.
__device__ __forceinline__ int gjf(int tid, int q) {
    return 4 * tid + 1024 * (q >> 2) + (q & 3);
}

__global__ __launch_bounds__(256, 8)
void phaseB_kernel(const int* __restrict__ labels) {
    __shared__ float vm[MAXM];
    __shared__ int jm[MAXM];
    __shared__ int cnt[MAXM];
    __shared__ float rv[8];
    __shared__ int ri[8];
    __shared__ int rm[8];
    __shared__ int mcount;
    __shared__ int widx;
    __shared__ int wsel;

    const float NEG_INF = __int_as_float(0xff800000);
    int tid = threadIdx.x, lane = tid & 31, wid = tid >> 5;
    int row = blockIdx.x;
    const float* simr = g_sim + (size_t)row * NB;
    int lr = labels[row];
    if (tid == 0) mcount = 0;
    __syncthreads();

    float ls[16];
    unsigned mrow = 0;
    #pragma unroll
    for (int t = 0; t < 4; t++) {
        int j4 = tid + 256 * t;
        float4 s4 = *(const float4*)(simr + 4 * (size_t)j4);
        int4 l4 = *(const int4*)(labels + 4 * j4);
        int b = 4 * t;
        ls[b + 0] = s4.x; ls[b + 1] = s4.y; ls[b + 2] = s4.z; ls[b + 3] = s4.w;
        if (l4.x == lr) mrow |= 1u << (b + 0);
        if (l4.y == lr) mrow |= 1u << (b + 1);
        if (l4.z == lr) mrow |= 1u << (b + 2);
        if (l4.w == lr) mrow |= 1u << (b + 3);
    }

    // Gather matched elements.
    #pragma unroll
    for (int q = 0; q < 16; q++) {
        if ((mrow >> q) & 1u) {
            int p = atomicAdd(&mcount, 1);
            if (p < MAXM) { jm[p] = gjf(tid, q); vm[p] = ls[q]; cnt[p] = 0; }
        }
    }
    __syncthreads();
    int k = mcount;
    if (k > MAXM) k = MAXM;

    // Count-based ranks for matched elements (rank = cnt+1, stable ties).
    for (int m = 0; m < k; m++) {
        float vmv = vm[m];
        int jmi = jm[m];
        int c = 0;
        #pragma unroll
        for (int q = 0; q < 16; q++)
            c += (ls[q] > vmv || (ls[q] == vmv && gjf(tid, q) < jmi)) ? 1 : 0;
        c = __reduce_add_sync(0xffffffffu, c);
        if (lane == 0) atomicAdd(&cnt[m], c);
    }

    // Per-warp maxima (value, index, match), stable tie-break on smaller index.
    auto warp_max = [&](float& bv, int& bi, int& bm) {
        bv = NEG_INF; bi = 1 << 30; bm = 0;
        #pragma unroll
        for (int q = 0; q < 16; q++) {
            float v = ls[q];
            int j = gjf(tid, q);
            if (v > bv || (v == bv && j < bi)) { bv = v; bi = j; bm = (mrow >> q) & 1; }
        }
        #pragma unroll
        for (int o = 16; o; o >>= 1) {
            float ov = __shfl_xor_sync(0xffffffffu, bv, o);
            int oi = __shfl_xor_sync(0xffffffffu, bi, o);
            int om = __shfl_xor_sync(0xffffffffu, bm, o);
            if (ov > bv || (ov == bv && oi < bi)) { bv = ov; bi = oi; bm = om; }
        }
    };

    {
        float bv; int bi2, bm;
        warp_max(bv, bi2, bm);
        if (lane == 0) { rv[wid] = bv; ri[wid] = bi2; rm[wid] = bm; }
    }
    __syncthreads();

    // Extract top-k; only the winning warp recomputes its max each step.
    float kf = (float)k;
    float fp_acc = 0.0f;  // tid 0 only
    for (int e = 1; e <= k; e++) {
        if (tid == 0) {
            float wv = rv[0]; int wi2 = ri[0]; int wm = rm[0]; int ws = 0;
            #pragma unroll
            for (int w = 1; w < 8; w++)
                if (rv[w] > wv || (rv[w] == wv && ri[w] < wi2)) {
                    wv = rv[w]; wi2 = ri[w]; wm = rm[w]; ws = w;
                }
            widx = wi2; wsel = ws;
            if (!wm)  // false positive at rank e
                fp_acc += wv * (0.5f + (kf - (float)e + 1.0f) / kf * 0.5f);
        }
        __syncthreads();
        int wi2 = widx;
        if (wid == wsel) {
            // owner thread clears its element, then the warp recomputes its max
            if (tid == ((wi2 >> 2) & 255)) {
                int q = 4 * (wi2 >> 10) + (wi2 & 3);
                ls[q] = NEG_INF;
            }
            float bv; int bi2, bm;
            warp_max(bv, bi2, bm);
            if (lane == 0) { rv[wid] = bv; ri[wid] = bi2; rm[wid] = bm; }
        }
        __syncthreads();
    }

    if (tid == 0) {
        float fn_acc = 0.0f;
        float nf = (float)NB;
        for (int m = 0; m < k; m++) {
            int rank = cnt[m] + 1;
            if (rank > k)
                fn_acc += vm[m] * (0.5f + ((float)rank - kf) / (nf - kf) * 0.5f);
        }
        atomicAdd(&g_accum, (double)(fp_acc - fn_acc));
    }
}

__global__ void out_kernel(float* out) {
    out[0] = (float)g_accum;
}

extern "C" void kernel_launch(void* const* d_in, const int* in_sizes, int n_in,
                              void* d_out, int out_size) {
    const float* X = (const float*)d_in[0];
    const int* labels = (const int*)d_in[1];
    float* out = (float*)d_out;

    size_t shmem = (size_t)4 * KC * LDW * 4   // As + Bs double-buffered
                 + 2 * TILE * 4               // sqA, sqB
                 + 2 * TILE * 4;              // lbA, lbB
    cudaFuncSetAttribute(gemm_sim_kernel,
                         cudaFuncAttributeMaxDynamicSharedMemorySize, (int)shmem);

    prep_kernel<<<NB / 8, 256>>>(X);
    gemm_sim_kernel<<<dim3(NB / TILE, NB / TILE), 256, shmem>>>(X, labels);
    phaseB_kernel<<<NB, 256>>>(labels);
    out_kernel<<<1, 1>>>(out);
}